// round 1
// baseline (speedup 1.0000x reference)
#include <cuda_runtime.h>
#include <cuda_bf16.h>
#include <math_constants.h>

// Problem constants
#define BATCH 2
#define SEQ   2048
#define DMODEL 1024
#define NHEADS 16
#define DK    64
#define BL    (BATCH*SEQ)          // 4096 rows

// Scratch: Q/K/V in [b,h,l,k] layout, ctx in [b,l,h*dk]
__device__ float g_Q[BATCH*NHEADS*SEQ*DK];
__device__ float g_K[BATCH*NHEADS*SEQ*DK];
__device__ float g_V[BATCH*NHEADS*SEQ*DK];
__device__ float g_ctx[BATCH*SEQ*DMODEL];

// ---------------------------------------------------------------------------
// Kernel 1: fused QKV projection.
//   C[b,h,l,k] = sum_d A[b,l,d] * W[h,d,k]
// GEMM view: M=4096 (b,l), N=1024 (h*64+k), K=1024.
// BN=64 tiles align exactly with heads -> weight panel is contiguous [D,64].
// Tiles: BM=64, BN=64, BK=16; 256 threads; 4x4 micro-tile per thread.
// ---------------------------------------------------------------------------
__global__ __launch_bounds__(256)
void qkv_proj_kernel(const float* __restrict__ q,
                     const float* __restrict__ k,
                     const float* __restrict__ v,
                     const float* __restrict__ wq,
                     const float* __restrict__ wk,
                     const float* __restrict__ wv)
{
    const int which = blockIdx.z;
    const float* A = (which == 0) ? q : (which == 1) ? k : v;
    const float* W = (which == 0) ? wq : (which == 1) ? wk : wv;
    float* C = (which == 0) ? g_Q : (which == 1) ? g_K : g_V;

    const int m0 = blockIdx.y * 64;
    const int h  = blockIdx.x;                 // BN=64 == one head
    const float* Wb = W + (size_t)h * DMODEL * DK;   // [d][kc], ld = 64

    __shared__ float As[16][65];   // As[kk][m]  (transposed, pad->conflict-free)
    __shared__ float Bs[16][64];   // Bs[kk][n]

    const int tid = threadIdx.x;
    const int tx = tid & 15, ty = tid >> 4;

    float acc[4][4] = {};

    for (int kt = 0; kt < DMODEL / 16; ++kt) {
        const int k0 = kt * 16;
        // load A tile (64x16) transposed into As
        #pragma unroll
        for (int i = tid; i < 64 * 16; i += 256) {
            int m = i >> 4, kk = i & 15;
            As[kk][m] = A[(size_t)(m0 + m) * DMODEL + k0 + kk];
        }
        // load W tile (16x64), coalesced
        #pragma unroll
        for (int i = tid; i < 16 * 64; i += 256) {
            int kk = i >> 6, n = i & 63;
            Bs[kk][n] = Wb[(size_t)(k0 + kk) * DK + n];
        }
        __syncthreads();
        #pragma unroll
        for (int kk = 0; kk < 16; ++kk) {
            float a[4], b[4];
            #pragma unroll
            for (int i = 0; i < 4; ++i) a[i] = As[kk][ty * 4 + i];
            #pragma unroll
            for (int j = 0; j < 4; ++j) b[j] = Bs[kk][tx * 4 + j];
            #pragma unroll
            for (int i = 0; i < 4; ++i)
                #pragma unroll
                for (int j = 0; j < 4; ++j)
                    acc[i][j] = fmaf(a[i], b[j], acc[i][j]);
        }
        __syncthreads();
    }

    // write to [b,h,l,k]
    #pragma unroll
    for (int i = 0; i < 4; ++i) {
        const int m = m0 + ty * 4 + i;
        const int b = m >> 11;          // /2048
        const int l = m & 2047;
        float* cp = C + (((size_t)(b * NHEADS + h) * SEQ) + l) * DK + tx * 4;
        #pragma unroll
        for (int j = 0; j < 4; ++j) cp[j] = acc[i][j];
    }
}

// ---------------------------------------------------------------------------
// Kernel 2: flash attention per (b,h). BR=BC=64, online softmax.
// Block: 256 threads (16x16), each owns a 4x4 micro-tile.
// Row statistics reduced across the 16 tx-lanes via half-warp shuffles.
// Scale 1/sqrt(64)=0.125 folded into the Q load. Phase bias skipped:
// it is constant along the softmax axis and cancels exactly.
// Shared: Qs,Ks,Vs,Ps each [64][65] -> 66560 B dynamic smem.
// ---------------------------------------------------------------------------
#define SA 65

__global__ __launch_bounds__(256)
void attn_kernel()
{
    extern __shared__ float sm[];
    float* Qs = sm;                  // [64][SA]
    float* Ks = sm + 64 * SA;
    float* Vs = sm + 2 * 64 * SA;
    float* Ps = sm + 3 * 64 * SA;

    const int tid = threadIdx.x;
    const int tx = tid & 15, ty = tid >> 4;
    const int qt = blockIdx.x;       // 0..31 query tile
    const int bh = blockIdx.y;       // 0..31 (b*16+h)

    const float* Qg = g_Q + (size_t)bh * SEQ * DK + (size_t)qt * 64 * DK;
    const float* Kg = g_K + (size_t)bh * SEQ * DK;
    const float* Vg = g_V + (size_t)bh * SEQ * DK;

    // load Q tile pre-scaled
    for (int i = tid; i < 64 * DK; i += 256)
        Qs[(i >> 6) * SA + (i & 63)] = Qg[i] * 0.125f;

    float acc[4][4] = {};
    float mrow[4], lrow[4];
    #pragma unroll
    for (int i = 0; i < 4; ++i) { mrow[i] = -1e30f; lrow[i] = 0.f; }

    __syncthreads();

    for (int kt = 0; kt < SEQ / 64; ++kt) {
        const float* kp = Kg + (size_t)kt * 64 * DK;
        const float* vp = Vg + (size_t)kt * 64 * DK;
        for (int i = tid; i < 64 * DK; i += 256) {
            int r = i >> 6, c = i & 63;
            Ks[r * SA + c] = kp[i];
            Vs[r * SA + c] = vp[i];
        }
        __syncthreads();

        // S = Q K^T  (4x4 per thread)
        float s[4][4] = {};
        #pragma unroll 8
        for (int k = 0; k < DK; ++k) {
            float a[4], b[4];
            #pragma unroll
            for (int i = 0; i < 4; ++i) a[i] = Qs[(ty * 4 + i) * SA + k];
            #pragma unroll
            for (int j = 0; j < 4; ++j) b[j] = Ks[(tx * 4 + j) * SA + k];
            #pragma unroll
            for (int i = 0; i < 4; ++i)
                #pragma unroll
                for (int j = 0; j < 4; ++j)
                    s[i][j] = fmaf(a[i], b[j], s[i][j]);
        }

        // online softmax update per row
        #pragma unroll
        for (int i = 0; i < 4; ++i) {
            float lm = fmaxf(fmaxf(s[i][0], s[i][1]), fmaxf(s[i][2], s[i][3]));
            #pragma unroll
            for (int off = 8; off > 0; off >>= 1)
                lm = fmaxf(lm, __shfl_xor_sync(0xffffffffu, lm, off));
            const float Mn = fmaxf(mrow[i], lm);
            const float corr = __expf(mrow[i] - Mn);
            float rs = 0.f;
            #pragma unroll
            for (int j = 0; j < 4; ++j) {
                s[i][j] = __expf(s[i][j] - Mn);
                rs += s[i][j];
            }
            #pragma unroll
            for (int off = 8; off > 0; off >>= 1)
                rs += __shfl_xor_sync(0xffffffffu, rs, off);
            lrow[i] = lrow[i] * corr + rs;
            mrow[i] = Mn;
            #pragma unroll
            for (int j = 0; j < 4; ++j) acc[i][j] *= corr;
            #pragma unroll
            for (int j = 0; j < 4; ++j)
                Ps[(ty * 4 + i) * SA + tx * 4 + j] = s[i][j];
        }
        __syncthreads();

        // O += P V
        #pragma unroll 8
        for (int k = 0; k < 64; ++k) {
            float a[4], b[4];
            #pragma unroll
            for (int i = 0; i < 4; ++i) a[i] = Ps[(ty * 4 + i) * SA + k];
            #pragma unroll
            for (int j = 0; j < 4; ++j) b[j] = Vs[k * SA + tx * 4 + j];
            #pragma unroll
            for (int i = 0; i < 4; ++i)
                #pragma unroll
                for (int j = 0; j < 4; ++j)
                    acc[i][j] = fmaf(a[i], b[j], acc[i][j]);
        }
        __syncthreads();
    }

    // normalize and write ctx[b][l][h*64+c]
    const int b = bh >> 4, h = bh & 15;
    const int l0 = qt * 64;
    #pragma unroll
    for (int i = 0; i < 4; ++i) {
        const float inv = 1.0f / lrow[i];
        float* cp = g_ctx + ((size_t)(b * SEQ + l0 + ty * 4 + i)) * DMODEL
                    + h * DK + tx * 4;
        #pragma unroll
        for (int j = 0; j < 4; ++j) cp[j] = acc[i][j] * inv;
    }
}

// ---------------------------------------------------------------------------
// Kernel 3: output projection. out[m][n] = ctx[m][:] @ out_w[:,n] + out_b[n]
// M=4096, N=1024, K=1024. Same tiling as kernel 1.
// ---------------------------------------------------------------------------
__global__ __launch_bounds__(256)
void out_proj_kernel(const float* __restrict__ out_w,
                     const float* __restrict__ out_b,
                     float* __restrict__ out)
{
    const int m0 = blockIdx.y * 64;
    const int n0 = blockIdx.x * 64;

    __shared__ float As[16][65];
    __shared__ float Bs[16][64];

    const int tid = threadIdx.x;
    const int tx = tid & 15, ty = tid >> 4;

    float acc[4][4] = {};

    for (int kt = 0; kt < DMODEL / 16; ++kt) {
        const int k0 = kt * 16;
        #pragma unroll
        for (int i = tid; i < 64 * 16; i += 256) {
            int m = i >> 4, kk = i & 15;
            As[kk][m] = g_ctx[(size_t)(m0 + m) * DMODEL + k0 + kk];
        }
        #pragma unroll
        for (int i = tid; i < 16 * 64; i += 256) {
            int kk = i >> 6, n = i & 63;
            Bs[kk][n] = out_w[(size_t)(k0 + kk) * DMODEL + n0 + n];
        }
        __syncthreads();
        #pragma unroll
        for (int kk = 0; kk < 16; ++kk) {
            float a[4], b[4];
            #pragma unroll
            for (int i = 0; i < 4; ++i) a[i] = As[kk][ty * 4 + i];
            #pragma unroll
            for (int j = 0; j < 4; ++j) b[j] = Bs[kk][tx * 4 + j];
            #pragma unroll
            for (int i = 0; i < 4; ++i)
                #pragma unroll
                for (int j = 0; j < 4; ++j)
                    acc[i][j] = fmaf(a[i], b[j], acc[i][j]);
        }
        __syncthreads();
    }

    #pragma unroll
    for (int i = 0; i < 4; ++i) {
        const int m = m0 + ty * 4 + i;
        float* op = out + (size_t)m * DMODEL + n0 + tx * 4;
        #pragma unroll
        for (int j = 0; j < 4; ++j)
            op[j] = acc[i][j] + out_b[n0 + tx * 4 + j];
    }
}

// ---------------------------------------------------------------------------
// Launch
// Inputs (metadata order): query, key, value, Wq, Wk, Wv, out_w, out_b, coupling
// Output: float [2,2048,1024]
// Note: the Kuramoto phase bias is constant along the softmax axis, so it
// cancels in softmax exactly -> coupling is (correctly) unused.
// ---------------------------------------------------------------------------
extern "C" void kernel_launch(void* const* d_in, const int* in_sizes, int n_in,
                              void* d_out, int out_size)
{
    const float* q     = (const float*)d_in[0];
    const float* k     = (const float*)d_in[1];
    const float* v     = (const float*)d_in[2];
    const float* wq    = (const float*)d_in[3];
    const float* wk    = (const float*)d_in[4];
    const float* wv    = (const float*)d_in[5];
    const float* out_w = (const float*)d_in[6];
    const float* out_b = (const float*)d_in[7];
    float* out = (float*)d_out;

    // QKV projection: N-tiles(16) x M-tiles(64) x {Q,K,V}
    qkv_proj_kernel<<<dim3(NHEADS, BL / 64, 3), 256>>>(q, k, v, wq, wk, wv);

    // attention: 32 q-tiles x 32 (b,h)
    const int smem = 4 * 64 * SA * sizeof(float);   // 66560 B
    static_assert(4 * 64 * SA * sizeof(float) == 66560, "smem");
    cudaFuncSetAttribute(attn_kernel,
                         cudaFuncAttributeMaxDynamicSharedMemorySize, smem);
    attn_kernel<<<dim3(SEQ / 64, BATCH * NHEADS), 256, smem>>>();

    // output projection
    out_proj_kernel<<<dim3(DMODEL / 64, BL / 64), 256>>>(out_w, out_b, out);
}